// round 5
// baseline (speedup 1.0000x reference)
#include <cuda_runtime.h>
#include <math.h>

#define N_JOINTS 50
#define ROW 150
#define ROWS_PER_BLK 32
#define THREADS 256
#define TOTAL_ROWS (128 * 1024)
#define N_BLOCKS (TOTAL_ROWS / ROWS_PER_BLK)      // 4096
#define ELEMS (ROWS_PER_BLK * ROW)                // 4800 (p,t) pairs per block
#define VECS (ELEMS / 4)                          // 1200 float4-groups

// Per-block partials, fully overwritten every launch.
__device__ float g_part_abs[N_BLOCKS];
__device__ float g_part_sq[N_BLOCKS];
// atomicInc wraps to 0 after N_BLOCKS increments -> deterministic across replays.
__device__ unsigned int g_count = 0;

__global__ __launch_bounds__(THREADS) void bone_loss_kernel(
    const float* __restrict__ preds,
    const float* __restrict__ targets,
    float* __restrict__ out)
{
    // Interleaved (p_masked, t) pairs: s[row*150 + c] = {p, t}
    __shared__ float2 s[ELEMS];
    __shared__ float s_abs[THREADS / 32];
    __shared__ float s_sq[THREADS / 32];
    __shared__ bool s_last;

    const int tid = threadIdx.x;
    const int wid = tid >> 5;
    const int lid = tid & 31;

    // ---- Phase 1: vectorized load + mask + interleaved stage + L1 term ----
    const long long vbase = (long long)blockIdx.x * VECS;
    const float4* __restrict__ p4 = (const float4*)preds + vbase;
    const float4* __restrict__ t4 = (const float4*)targets + vbase;
    float4* s4 = (float4*)s;   // 2 float4 per group of 4 pairs

    float abs_sum = 0.0f;
    for (int i = tid; i < VECS; i += THREADS) {
        float4 t = __ldg(t4 + i);
        float4 p = __ldg(p4 + i);
        float4 pm;
        pm.x = (t.x != 0.0f) ? p.x : 0.0f;
        pm.y = (t.y != 0.0f) ? p.y : 0.0f;
        pm.z = (t.z != 0.0f) ? p.z : 0.0f;
        pm.w = (t.w != 0.0f) ? p.w : 0.0f;
        // pairs s[4i+k] = {pm_k, t_k}  ->  two 16B stores
        s4[2 * i]     = make_float4(pm.x, t.x, pm.y, t.y);
        s4[2 * i + 1] = make_float4(pm.z, t.z, pm.w, t.w);
        abs_sum += fabsf(pm.x - t.x) + fabsf(pm.y - t.y)
                 + fabsf(pm.z - t.z) + fabsf(pm.w - t.w);
    }
    __syncthreads();

    // ---- Phase 2: 8 threads per row, sequential bones with register reuse ----
    const int sub = tid & 7;        // 0..7
    const int row = tid >> 3;       // 0..31
    // bone ranges: sub0:[0,7) sub1..6: 6 each, sub7:[43,50)
    const int start = (sub == 0) ? 0 : 7 + 6 * (sub - 1);
    const int cnt   = (sub == 0 || sub == 7) ? 7 : 6;

    const float2* __restrict__ srow = s + row * ROW;

    float sq_sum = 0.0f;
    // joint 'a' = start
    float2 a0 = srow[3 * start];
    float2 a1 = srow[3 * start + 1];
    float2 a2 = srow[3 * start + 2];

    for (int b = start; b < start + cnt; b++) {
        int nj = b + 1; if (nj == N_JOINTS) nj = 0;
        float2 b0 = srow[3 * nj];
        float2 b1 = srow[3 * nj + 1];
        float2 b2 = srow[3 * nj + 2];

        float pd0 = a0.x - b0.x, td0 = a0.y - b0.y;
        float pd1 = a1.x - b1.x, td1 = a1.y - b1.y;
        float pd2 = a2.x - b2.x, td2 = a2.y - b2.y;

        float pdot = fmaf(pd0, pd0, fmaf(pd1, pd1, pd2 * pd2));
        float tdot = fmaf(td0, td0, fmaf(td1, td1, td2 * td2));
        // rsqrt(d) == 1/(sqrt(d)+tiny) to ~3ulp for d>0; if d==0 diffs are 0,
        // pinv=0 reproduces the reference's 0 exactly.
        float pinv = (pdot > 0.0f) ? rsqrtf(pdot) : 0.0f;
        float tinv = (tdot > 0.0f) ? rsqrtf(tdot) : 0.0f;

        float x0 = fmaf(pd0, pinv, -(td0 * tinv));
        float x1 = fmaf(pd1, pinv, -(td1 * tinv));
        float x2 = fmaf(pd2, pinv, -(td2 * tinv));

        if (a0.y != 0.0f) sq_sum = fmaf(x0, x0, sq_sum);
        if (a1.y != 0.0f) sq_sum = fmaf(x1, x1, sq_sum);
        if (a2.y != 0.0f) sq_sum = fmaf(x2, x2, sq_sum);

        a0 = b0; a1 = b1; a2 = b2;   // slide: joint b becomes next joint a
    }

    // ---- warp + block reduction ----
    #pragma unroll
    for (int off = 16; off > 0; off >>= 1) {
        abs_sum += __shfl_down_sync(0xFFFFFFFFu, abs_sum, off);
        sq_sum  += __shfl_down_sync(0xFFFFFFFFu, sq_sum,  off);
    }
    if (lid == 0) { s_abs[wid] = abs_sum; s_sq[wid] = sq_sum; }
    __syncthreads();

    // ---- publish partial, detect last block ----
    if (tid == 0) {
        float ba = 0.0f, bs = 0.0f;
        #pragma unroll
        for (int w = 0; w < THREADS / 32; w++) { ba += s_abs[w]; bs += s_sq[w]; }
        g_part_abs[blockIdx.x] = ba;
        g_part_sq[blockIdx.x]  = bs;
        __threadfence();
        unsigned int v = atomicInc(&g_count, N_BLOCKS - 1); // wraps to 0 on last
        s_last = (v == N_BLOCKS - 1);
    }
    __syncthreads();

    // ---- last block: final reduction over all partials (L2-resident) ----
    if (s_last) {
        double a = 0.0, sdb = 0.0;
        for (int i = tid; i < N_BLOCKS; i += THREADS) {
            a   += (double)g_part_abs[i];
            sdb += (double)g_part_sq[i];
        }
        #pragma unroll
        for (int off = 16; off > 0; off >>= 1) {
            a   += __shfl_down_sync(0xFFFFFFFFu, a, off);
            sdb += __shfl_down_sync(0xFFFFFFFFu, sdb, off);
        }
        __shared__ double sh_a[THREADS / 32], sh_s[THREADS / 32];
        if (lid == 0) { sh_a[wid] = a; sh_s[wid] = sdb; }
        __syncthreads();
        if (tid == 0) {
            double ta = 0.0, ts = 0.0;
            #pragma unroll
            for (int w = 0; w < THREADS / 32; w++) { ta += sh_a[w]; ts += sh_s[w]; }
            const double N = (double)TOTAL_ROWS * (double)ROW;
            out[0] = (float)((ta / N + 0.1 * (ts / N)) * 0.1);
        }
    }
}

extern "C" void kernel_launch(void* const* d_in, const int* in_sizes, int n_in,
                              void* d_out, int out_size) {
    const float* preds   = (const float*)d_in[0];
    const float* targets = (const float*)d_in[1];
    float* out = (float*)d_out;

    bone_loss_kernel<<<N_BLOCKS, THREADS>>>(preds, targets, out);
}

// round 6
// speedup vs baseline: 1.0060x; 1.0060x over previous
#include <cuda_runtime.h>
#include <math.h>

#define N_JOINTS 50
#define ROW 150
#define ROWS_PER_BLK 16
#define THREADS 256
#define TOTAL_ROWS (128 * 1024)
#define N_BLOCKS (TOTAL_ROWS / ROWS_PER_BLK)      // 8192
#define ELEMS (ROWS_PER_BLK * ROW)                // 2400 (p,t) pairs per block
#define VECS (ELEMS / 4)                          // 600 float4-groups

// Per-block partials, fully overwritten every launch.
__device__ float g_part_abs[N_BLOCKS];
__device__ float g_part_sq[N_BLOCKS];
// atomicInc wraps to 0 after N_BLOCKS increments -> deterministic across replays.
__device__ unsigned int g_count = 0;

__global__ __launch_bounds__(THREADS, 7) void bone_loss_kernel(
    const float* __restrict__ preds,
    const float* __restrict__ targets,
    float* __restrict__ out)
{
    // Interleaved (p_masked, t) pairs: s[row*150 + c] = {p, t}
    __shared__ float2 s[ELEMS];
    __shared__ float s_abs[THREADS / 32];
    __shared__ float s_sq[THREADS / 32];
    __shared__ bool s_last;

    const int tid = threadIdx.x;
    const int wid = tid >> 5;
    const int lid = tid & 31;

    // ---- Phase 1: vectorized load + mask + interleaved stage + L1 term ----
    const long long vbase = (long long)blockIdx.x * VECS;
    const float4* __restrict__ p4 = (const float4*)preds + vbase;
    const float4* __restrict__ t4 = (const float4*)targets + vbase;
    float4* s4 = (float4*)s;   // 2 float4 per group of 4 pairs

    float abs_sum = 0.0f;
    for (int i = tid; i < VECS; i += THREADS) {
        float4 t = __ldg(t4 + i);
        float4 p = __ldg(p4 + i);
        float4 pm;
        pm.x = (t.x != 0.0f) ? p.x : 0.0f;
        pm.y = (t.y != 0.0f) ? p.y : 0.0f;
        pm.z = (t.z != 0.0f) ? p.z : 0.0f;
        pm.w = (t.w != 0.0f) ? p.w : 0.0f;
        s4[2 * i]     = make_float4(pm.x, t.x, pm.y, t.y);
        s4[2 * i + 1] = make_float4(pm.z, t.z, pm.w, t.w);
        abs_sum += fabsf(pm.x - t.x) + fabsf(pm.y - t.y)
                 + fabsf(pm.z - t.z) + fabsf(pm.w - t.w);
    }
    __syncthreads();

    // ---- Phase 2: each warp owns 2 rows = 100 bones; independent bones per lane ----
    const float2* __restrict__ spair = s + (wid * 2) * ROW;
    float sq_sum = 0.0f;
    #pragma unroll
    for (int it = 0; it < 4; it++) {
        const int idx = lid + it * 32;
        if (idx < 2 * N_JOINTS) {
            const int r  = (idx >= N_JOINTS) ? 1 : 0;      // row within pair
            const int bi = idx - r * N_JOINTS;             // bone in row
            const int nj = (bi + 1 == N_JOINTS) ? 0 : bi + 1;
            const float2* __restrict__ srow = spair + r * ROW;
            const int a = 3 * bi;
            const int b = 3 * nj;

            float2 a0 = srow[a],     a1 = srow[a + 1], a2 = srow[a + 2];
            float2 b0 = srow[b],     b1 = srow[b + 1], b2 = srow[b + 2];

            float pd0 = a0.x - b0.x, td0 = a0.y - b0.y;
            float pd1 = a1.x - b1.x, td1 = a1.y - b1.y;
            float pd2 = a2.x - b2.x, td2 = a2.y - b2.y;

            float pdot = fmaf(pd0, pd0, fmaf(pd1, pd1, pd2 * pd2));
            float tdot = fmaf(td0, td0, fmaf(td1, td1, td2 * td2));
            // rsqrt(d) == 1/(sqrt(d)+tiny) to ~3ulp for d>0; if d==0 all diffs
            // are 0 so pinv=0 reproduces the reference's 0 exactly.
            float pinv = (pdot > 0.0f) ? rsqrtf(pdot) : 0.0f;
            float tinv = (tdot > 0.0f) ? rsqrtf(tdot) : 0.0f;

            float x0 = fmaf(pd0, pinv, -(td0 * tinv));
            float x1 = fmaf(pd1, pinv, -(td1 * tinv));
            float x2 = fmaf(pd2, pinv, -(td2 * tinv));

            if (a0.y != 0.0f) sq_sum = fmaf(x0, x0, sq_sum);
            if (a1.y != 0.0f) sq_sum = fmaf(x1, x1, sq_sum);
            if (a2.y != 0.0f) sq_sum = fmaf(x2, x2, sq_sum);
        }
    }

    // ---- warp + block reduction ----
    #pragma unroll
    for (int off = 16; off > 0; off >>= 1) {
        abs_sum += __shfl_down_sync(0xFFFFFFFFu, abs_sum, off);
        sq_sum  += __shfl_down_sync(0xFFFFFFFFu, sq_sum,  off);
    }
    if (lid == 0) { s_abs[wid] = abs_sum; s_sq[wid] = sq_sum; }
    __syncthreads();

    // ---- publish partial, detect last block ----
    if (tid == 0) {
        float ba = 0.0f, bs = 0.0f;
        #pragma unroll
        for (int w = 0; w < THREADS / 32; w++) { ba += s_abs[w]; bs += s_sq[w]; }
        g_part_abs[blockIdx.x] = ba;
        g_part_sq[blockIdx.x]  = bs;
        __threadfence();
        unsigned int v = atomicInc(&g_count, N_BLOCKS - 1); // wraps to 0 on last
        s_last = (v == N_BLOCKS - 1);
    }
    __syncthreads();

    // ---- last block: final reduction over all partials (L2-resident) ----
    if (s_last) {
        double a = 0.0, sdb = 0.0;
        for (int i = tid; i < N_BLOCKS; i += THREADS) {
            a   += (double)g_part_abs[i];
            sdb += (double)g_part_sq[i];
        }
        #pragma unroll
        for (int off = 16; off > 0; off >>= 1) {
            a   += __shfl_down_sync(0xFFFFFFFFu, a, off);
            sdb += __shfl_down_sync(0xFFFFFFFFu, sdb, off);
        }
        __shared__ double sh_a[THREADS / 32], sh_s[THREADS / 32];
        if (lid == 0) { sh_a[wid] = a; sh_s[wid] = sdb; }
        __syncthreads();
        if (tid == 0) {
            double ta = 0.0, ts = 0.0;
            #pragma unroll
            for (int w = 0; w < THREADS / 32; w++) { ta += sh_a[w]; ts += sh_s[w]; }
            const double N = (double)TOTAL_ROWS * (double)ROW;
            out[0] = (float)((ta / N + 0.1 * (ts / N)) * 0.1);
        }
    }
}

extern "C" void kernel_launch(void* const* d_in, const int* in_sizes, int n_in,
                              void* d_out, int out_size) {
    const float* preds   = (const float*)d_in[0];
    const float* targets = (const float*)d_in[1];
    float* out = (float*)d_out;

    bone_loss_kernel<<<N_BLOCKS, THREADS>>>(preds, targets, out);
}

// round 7
// speedup vs baseline: 1.0402x; 1.0341x over previous
#include <cuda_runtime.h>
#include <math.h>

#define N_JOINTS 50
#define ROW 150
#define ROWS_PER_BLK 16
#define THREADS 256
#define TOTAL_ROWS (128 * 1024)
#define N_BLOCKS (TOTAL_ROWS / ROWS_PER_BLK)      // 8192
#define ELEMS (ROWS_PER_BLK * ROW)                // 2400 floats per tensor per block
#define VECS (ELEMS / 4)                          // 600 float4

// Per-block partials, fully overwritten every launch.
__device__ float g_part_abs[N_BLOCKS];
__device__ float g_part_sq[N_BLOCKS];
// atomicInc wraps to 0 after N_BLOCKS increments -> deterministic across replays.
__device__ unsigned int g_count = 0;

__global__ __launch_bounds__(THREADS) void bone_loss_kernel(
    const float* __restrict__ preds,
    const float* __restrict__ targets,
    float* __restrict__ out)
{
    // Separate arrays: stride-1 float4 stores (conflict-free),
    // stride-3 scalar loads in phase 2 (gcd(3,32)=1, conflict-free).
    __shared__ float sp[ELEMS];
    __shared__ float st[ELEMS];
    __shared__ float s_abs[THREADS / 32];
    __shared__ float s_sq[THREADS / 32];
    __shared__ bool s_last;

    const int tid = threadIdx.x;
    const int wid = tid >> 5;
    const int lid = tid & 31;

    // ---- Phase 1: vectorized load + mask + stage + L1 term ----
    const long long vbase = (long long)blockIdx.x * VECS;
    const float4* __restrict__ p4 = (const float4*)preds + vbase;
    const float4* __restrict__ t4 = (const float4*)targets + vbase;
    float4* sp4 = (float4*)sp;
    float4* st4 = (float4*)st;

    float abs_sum = 0.0f;
    for (int i = tid; i < VECS; i += THREADS) {
        float4 t = __ldg(t4 + i);
        float4 p = __ldg(p4 + i);
        float4 pm;
        pm.x = (t.x != 0.0f) ? p.x : 0.0f;
        pm.y = (t.y != 0.0f) ? p.y : 0.0f;
        pm.z = (t.z != 0.0f) ? p.z : 0.0f;
        pm.w = (t.w != 0.0f) ? p.w : 0.0f;
        sp4[i] = pm;
        st4[i] = t;   // t is already 0 exactly where mask==0
        abs_sum += fabsf(pm.x - t.x) + fabsf(pm.y - t.y)
                 + fabsf(pm.z - t.z) + fabsf(pm.w - t.w);
    }
    __syncthreads();

    // ---- Phase 2: warp owns 2 rows = 100 bones; independent bones per lane ----
    const int base = (wid * 2) * ROW;
    float sq_sum = 0.0f;
    #pragma unroll
    for (int it = 0; it < 4; it++) {
        const int idx = lid + it * 32;
        if (idx < 2 * N_JOINTS) {
            const int r  = (idx >= N_JOINTS) ? 1 : 0;     // row within pair (compare, no div)
            const int bi = idx - r * N_JOINTS;
            const int nj = (bi + 1 == N_JOINTS) ? 0 : bi + 1;
            const int roff = base + r * ROW;
            const int a = roff + 3 * bi;
            const int b = roff + 3 * nj;

            float pd0 = sp[a]     - sp[b];
            float pd1 = sp[a + 1] - sp[b + 1];
            float pd2 = sp[a + 2] - sp[b + 2];
            float ta0 = st[a], ta1 = st[a + 1], ta2 = st[a + 2];
            float td0 = ta0 - st[b];
            float td1 = ta1 - st[b + 1];
            float td2 = ta2 - st[b + 2];

            float pdot = fmaf(pd0, pd0, fmaf(pd1, pd1, pd2 * pd2));
            float tdot = fmaf(td0, td0, fmaf(td1, td1, td2 * td2));
            // rsqrt(d) == 1/(sqrt(d)+tiny) to ~3ulp for d>0; if d==0 all diffs
            // are 0 so pinv=0 reproduces the reference's 0 exactly.
            float pinv = (pdot > 0.0f) ? rsqrtf(pdot) : 0.0f;
            float tinv = (tdot > 0.0f) ? rsqrtf(tdot) : 0.0f;

            float x0 = fmaf(pd0, pinv, -(td0 * tinv));
            float x1 = fmaf(pd1, pinv, -(td1 * tinv));
            float x2 = fmaf(pd2, pinv, -(td2 * tinv));

            if (ta0 != 0.0f) sq_sum = fmaf(x0, x0, sq_sum);
            if (ta1 != 0.0f) sq_sum = fmaf(x1, x1, sq_sum);
            if (ta2 != 0.0f) sq_sum = fmaf(x2, x2, sq_sum);
        }
    }

    // ---- warp + block reduction ----
    #pragma unroll
    for (int off = 16; off > 0; off >>= 1) {
        abs_sum += __shfl_down_sync(0xFFFFFFFFu, abs_sum, off);
        sq_sum  += __shfl_down_sync(0xFFFFFFFFu, sq_sum,  off);
    }
    if (lid == 0) { s_abs[wid] = abs_sum; s_sq[wid] = sq_sum; }
    __syncthreads();

    // ---- publish partial, detect last block ----
    if (tid == 0) {
        float ba = 0.0f, bs = 0.0f;
        #pragma unroll
        for (int w = 0; w < THREADS / 32; w++) { ba += s_abs[w]; bs += s_sq[w]; }
        g_part_abs[blockIdx.x] = ba;
        g_part_sq[blockIdx.x]  = bs;
        __threadfence();
        unsigned int v = atomicInc(&g_count, N_BLOCKS - 1); // wraps to 0 on last
        s_last = (v == N_BLOCKS - 1);
    }
    __syncthreads();

    // ---- last block: final reduction over all partials (L2-resident) ----
    if (s_last) {
        double a = 0.0, sdb = 0.0;
        for (int i = tid; i < N_BLOCKS; i += THREADS) {
            a   += (double)g_part_abs[i];
            sdb += (double)g_part_sq[i];
        }
        #pragma unroll
        for (int off = 16; off > 0; off >>= 1) {
            a   += __shfl_down_sync(0xFFFFFFFFu, a, off);
            sdb += __shfl_down_sync(0xFFFFFFFFu, sdb, off);
        }
        __shared__ double sh_a[THREADS / 32], sh_s[THREADS / 32];
        if (lid == 0) { sh_a[wid] = a; sh_s[wid] = sdb; }
        __syncthreads();
        if (tid == 0) {
            double ta = 0.0, ts = 0.0;
            #pragma unroll
            for (int w = 0; w < THREADS / 32; w++) { ta += sh_a[w]; ts += sh_s[w]; }
            const double N = (double)TOTAL_ROWS * (double)ROW;
            out[0] = (float)((ta / N + 0.1 * (ts / N)) * 0.1);
        }
    }
}

extern "C" void kernel_launch(void* const* d_in, const int* in_sizes, int n_in,
                              void* d_out, int out_size) {
    const float* preds   = (const float*)d_in[0];
    const float* targets = (const float*)d_in[1];
    float* out = (float*)d_out;

    bone_loss_kernel<<<N_BLOCKS, THREADS>>>(preds, targets, out);
}